// round 1
// baseline (speedup 1.0000x reference)
#include <cuda_runtime.h>
#include <cuda_fp16.h>
#include <stdint.h>
#include <math.h>

// ---------------- problem constants ----------------
#define N_TOK 32768      // B*T = 4*8192
#define C_DIM 1024
#define HS    2048
#define HR    1024
#define NE    8

// ---------------- GEMM tile config ----------------
#define BM 128
#define BN 128
#define BK 32
#define ASTR (BK + 8)    // 40 halfs/row  (80B, conflict-free for ldmatrix)
#define BSTR (BN + 8)    // 136 halfs/row (272B, conflict-free for ldmatrix.trans)

// ---------------- static scratch (no allocations allowed) ----------------
__device__ __half g_xh[N_TOK * C_DIM];          // x in fp16
__device__ __half g_sw1h[C_DIM * HS];
__device__ __half g_sw3h[C_DIM * HS];
__device__ __half g_sw2h[HS * C_DIM];
__device__ __half g_w1h[NE * C_DIM * HR];
__device__ __half g_w2h[NE * HR * C_DIM];
__device__ __half g_H1[N_TOK * HS];             // silu(x@sw1+b1)
__device__ __half g_H2[N_TOK * HS];             // H1 * (x@sw3+b3)
__device__ __half g_Hr[2 * N_TOK * HR];         // routed hidden, grouped [k][r][4096][HR]

// ---------------- small PTX helpers ----------------
__device__ __forceinline__ void cp16(void* s, const void* g) {
    unsigned sa = (unsigned)__cvta_generic_to_shared(s);
    asm volatile("cp.async.cg.shared.global [%0], [%1], 16;" :: "r"(sa), "l"(g));
}
__device__ __forceinline__ void ldsm4(uint32_t* r, const __half* p) {
    unsigned a = (unsigned)__cvta_generic_to_shared(p);
    asm volatile("ldmatrix.sync.aligned.m8n8.x4.shared.b16 {%0,%1,%2,%3}, [%4];"
                 : "=r"(r[0]), "=r"(r[1]), "=r"(r[2]), "=r"(r[3]) : "r"(a));
}
__device__ __forceinline__ void ldsm4t(uint32_t* r, const __half* p) {
    unsigned a = (unsigned)__cvta_generic_to_shared(p);
    asm volatile("ldmatrix.sync.aligned.m8n8.x4.trans.shared.b16 {%0,%1,%2,%3}, [%4];"
                 : "=r"(r[0]), "=r"(r[1]), "=r"(r[2]), "=r"(r[3]) : "r"(a));
}
__device__ __forceinline__ void mma16816(float* d, const uint32_t* a, const uint32_t* b) {
    asm volatile(
        "mma.sync.aligned.m16n8k16.row.col.f32.f16.f16.f32 "
        "{%0,%1,%2,%3},{%4,%5,%6,%7},{%8,%9},{%0,%1,%2,%3};"
        : "+f"(d[0]), "+f"(d[1]), "+f"(d[2]), "+f"(d[3])
        : "r"(a[0]), "r"(a[1]), "r"(a[2]), "r"(a[3]), "r"(b[0]), "r"(b[1]));
}

// ---------------- conversion kernel (fp32 -> fp16, vectorized x4) ----------------
__device__ __forceinline__ __half* conv_dst(int tag) {
    switch (tag) {
        case 0: return g_xh;
        case 1: return g_sw1h;
        case 2: return g_sw3h;
        case 3: return g_sw2h;
        case 4: return g_w1h;
        default: return g_w2h;
    }
}
__global__ void k_convert(const float* __restrict__ src, int tag, int n4) {
    int i = blockIdx.x * blockDim.x + threadIdx.x;
    if (i >= n4) return;
    float4 v = ((const float4*)src)[i];
    __half2* d = (__half2*)conv_dst(tag);
    d[2 * i]     = __floats2half2_rn(v.x, v.y);
    d[2 * i + 1] = __floats2half2_rn(v.z, v.w);
}

// ---------------- tile prefetch (cp.async) ----------------
__device__ __forceinline__ void prefetch_tile(
    const __half* __restrict__ A, int strideA,
    const __half* __restrict__ B, int ldb,
    int m0, int n0, int kt, __half* Asb, __half* Bsb, int tid)
{
#pragma unroll
    for (int i = 0; i < 2; i++) {              // A: 128x32 halfs = 512 x 16B chunks
        int c = tid + i * 256;
        int ar = c >> 2, ac = c & 3;
        cp16(Asb + ar * ASTR + ac * 8,
             A + (size_t)(m0 + ar) * strideA + kt * BK + ac * 8);
    }
#pragma unroll
    for (int i = 0; i < 2; i++) {              // B: 32x128 halfs = 512 x 16B chunks
        int c = tid + i * 256;
        int br = c >> 4, bc = c & 15;
        cp16(Bsb + br * BSTR + bc * 8,
             B + (size_t)(kt * BK + br) * ldb + n0 + bc * 8);
    }
}

// ---------------- fused GEMM core ----------------
// MODE 0: out(h) = silu(acc+bias)
// MODE 1: out(h) = aux * (acc+bias)
// MODE 2: out(f) = 0.5*(acc+bias)          (assign)
// MODE 3: out(h) = gelu_exact(acc+bias)
// MODE 4: out(f) += 0.25*(acc+bias)
template <int MODE>
__device__ __forceinline__ void gemm_core(
    const __half* __restrict__ A, int strideA,
    const __half* __restrict__ B, int ldb,
    const float* __restrict__ bias,
    const __half* __restrict__ aux, int strideAux,
    void* __restrict__ outp, int strideOut,
    int K)
{
    __shared__ __align__(16) __half As[2][BM * ASTR];
    __shared__ __align__(16) __half Bs[2][BK * BSTR];

    const int tid = threadIdx.x;
    const int m0 = blockIdx.y * BM;
    const int n0 = blockIdx.x * BN;
    const int KT = K / BK;

    prefetch_tile(A, strideA, B, ldb, m0, n0, 0, As[0], Bs[0], tid);
    asm volatile("cp.async.commit_group;");
    prefetch_tile(A, strideA, B, ldb, m0, n0, 1, As[1], Bs[1], tid);
    asm volatile("cp.async.commit_group;");

    float acc[2][8][4];
#pragma unroll
    for (int i = 0; i < 2; i++)
#pragma unroll
        for (int j = 0; j < 8; j++)
#pragma unroll
            for (int e = 0; e < 4; e++) acc[i][j][e] = 0.f;

    const int warp = tid >> 5, lane = tid & 31;
    const int wm = warp & 3, wn = warp >> 2;   // warp tile: 32 rows x 64 cols

    for (int kt = 0; kt < KT; ++kt) {
        const int st = kt & 1;
        asm volatile("cp.async.wait_group 1;");
        __syncthreads();

#pragma unroll
        for (int s = 0; s < 2; s++) {          // two k16 steps per BK=32
            uint32_t a[2][4], b[4][4];
#pragma unroll
            for (int mi = 0; mi < 2; mi++) {
                const __half* p = &As[st][(wm * 32 + mi * 16 + (lane & 15)) * ASTR
                                          + s * 16 + (lane >> 4) * 8];
                ldsm4(a[mi], p);
            }
#pragma unroll
            for (int p4 = 0; p4 < 4; p4++) {   // 16 cols per ldmatrix.x4.trans
                const __half* p = &Bs[st][(s * 16 + (lane & 7) + ((lane >> 3) & 1) * 8) * BSTR
                                          + wn * 64 + p4 * 16 + (lane >> 4) * 8];
                ldsm4t(b[p4], p);
            }
#pragma unroll
            for (int mi = 0; mi < 2; mi++)
#pragma unroll
                for (int ni = 0; ni < 8; ni++)
                    mma16816(acc[mi][ni], a[mi], &b[ni >> 1][(ni & 1) * 2]);
        }
        __syncthreads();
        if (kt + 2 < KT)
            prefetch_tile(A, strideA, B, ldb, m0, n0, kt + 2, As[st], Bs[st], tid);
        asm volatile("cp.async.commit_group;");
    }

    // ---- epilogue ----
#pragma unroll
    for (int mi = 0; mi < 2; mi++)
#pragma unroll
        for (int ni = 0; ni < 8; ni++)
#pragma unroll
            for (int pp = 0; pp < 2; pp++) {
                int row = m0 + wm * 32 + mi * 16 + (lane >> 2) + pp * 8;
                int col = n0 + wn * 64 + ni * 8 + (lane & 3) * 2;
                float v0 = acc[mi][ni][2 * pp + 0] + bias[col];
                float v1 = acc[mi][ni][2 * pp + 1] + bias[col + 1];
                if constexpr (MODE == 0) {
                    v0 = v0 / (1.f + __expf(-v0));
                    v1 = v1 / (1.f + __expf(-v1));
                    *(__half2*)((__half*)outp + (size_t)row * strideOut + col) =
                        __floats2half2_rn(v0, v1);
                } else if constexpr (MODE == 1) {
                    __half2 g = *(const __half2*)(aux + (size_t)row * strideAux + col);
                    v0 *= __low2float(g);
                    v1 *= __high2float(g);
                    *(__half2*)((__half*)outp + (size_t)row * strideOut + col) =
                        __floats2half2_rn(v0, v1);
                } else if constexpr (MODE == 2) {
                    float2 f; f.x = 0.5f * v0; f.y = 0.5f * v1;
                    *(float2*)((float*)outp + (size_t)row * strideOut + col) = f;
                } else if constexpr (MODE == 3) {
                    v0 = 0.5f * v0 * (1.f + erff(v0 * 0.70710678118654752f));
                    v1 = 0.5f * v1 * (1.f + erff(v1 * 0.70710678118654752f));
                    *(__half2*)((__half*)outp + (size_t)row * strideOut + col) =
                        __floats2half2_rn(v0, v1);
                } else {
                    float* o = (float*)outp + (size_t)row * strideOut + col;
                    float2 f = *(float2*)o;
                    f.x += 0.25f * v0; f.y += 0.25f * v1;
                    *(float2*)o = f;
                }
            }
}

// ---------------- kernel wrappers ----------------
__global__ __launch_bounds__(256, 1) void k_up1(const float* __restrict__ sb1) {
    gemm_core<0>(g_xh, C_DIM, g_sw1h, HS, sb1, nullptr, 0, g_H1, HS, C_DIM);
}
__global__ __launch_bounds__(256, 1) void k_up3(const float* __restrict__ sb3) {
    gemm_core<1>(g_xh, C_DIM, g_sw3h, HS, sb3, g_H1, HS, g_H2, HS, C_DIM);
}
__global__ __launch_bounds__(256, 1) void k_down_shared(const float* __restrict__ sb2,
                                                        float* __restrict__ dout) {
    gemm_core<2>(g_H2, HS, g_sw2h, C_DIM, sb2, nullptr, 0, dout, C_DIM, HS);
}
// residue class r (= token mod 8), hash slot k: expert e = (3r + 7k) mod 8.
// A rows are token t = r + 8*j  (j = logical row) -> strided access, no gather needed.
__global__ __launch_bounds__(256, 1) void k_routed_up(const float* __restrict__ b1) {
    int z = blockIdx.z;                 // z = kk*8 + rr
    int rr = z & 7, kk = z >> 3;
    int e = (3 * rr + 7 * kk) & 7;
    gemm_core<3>(g_xh + rr * C_DIM, 8 * C_DIM,
                 g_w1h + (size_t)e * C_DIM * HR, HR,
                 b1 + e * HR, nullptr, 0,
                 g_Hr + (size_t)z * 4096 * HR, HR, C_DIM);
}
__global__ __launch_bounds__(256, 1) void k_routed_down(const float* __restrict__ b2,
                                                        float* __restrict__ dout, int kk) {
    int rr = blockIdx.z;
    int e = (3 * rr + 7 * kk) & 7;
    int z = kk * 8 + rr;
    gemm_core<4>(g_Hr + (size_t)z * 4096 * HR, HR,
                 g_w2h + (size_t)e * HR * C_DIM, C_DIM,
                 b2 + e * C_DIM, nullptr, 0,
                 dout + rr * C_DIM, 8 * C_DIM, HR);
}

// ---------------- launch ----------------
extern "C" void kernel_launch(void* const* d_in, const int* in_sizes, int n_in,
                              void* d_out, int out_size) {
    const float* x   = (const float*)d_in[0];
    // d_in[1] = t_emb : unused by reference
    const float* sw1 = (const float*)d_in[2];
    const float* sb1 = (const float*)d_in[3];
    const float* sw3 = (const float*)d_in[4];
    const float* sb3 = (const float*)d_in[5];
    const float* sw2 = (const float*)d_in[6];
    const float* sb2 = (const float*)d_in[7];
    const float* w1  = (const float*)d_in[8];
    const float* b1  = (const float*)d_in[9];
    const float* w2  = (const float*)d_in[10];
    const float* b2  = (const float*)d_in[11];
    float* out = (float*)d_out;

    // fp32 -> fp16 conversions (deterministic each call)
    {
        struct { const float* p; int tag; int n; } cv[6] = {
            { x,   0, N_TOK * C_DIM },
            { sw1, 1, C_DIM * HS },
            { sw3, 2, C_DIM * HS },
            { sw2, 3, HS * C_DIM },
            { w1,  4, NE * C_DIM * HR },
            { w2,  5, NE * HR * C_DIM },
        };
        for (int i = 0; i < 6; i++) {
            int n4 = cv[i].n / 4;
            k_convert<<<(n4 + 255) / 256, 256>>>(cv[i].p, cv[i].tag, n4);
        }
    }

    // shared SwiGLU expert
    k_up1<<<dim3(HS / BN, N_TOK / BM), 256>>>(sb1);
    k_up3<<<dim3(HS / BN, N_TOK / BM), 256>>>(sb3);
    k_down_shared<<<dim3(C_DIM / BN, N_TOK / BM), 256>>>(sb2, out);

    // routed experts: 16 group-GEMMs up (parallel, disjoint outputs),
    // down split by k (both k's accumulate into the same token rows)
    k_routed_up<<<dim3(HR / BN, 4096 / BM, 16), 256>>>(b1);
    k_routed_down<<<dim3(C_DIM / BN, 4096 / BM, 8), 256>>>(b2, out, 0);
    k_routed_down<<<dim3(C_DIM / BN, 4096 / BM, 8), 256>>>(b2, out, 1);
}